// round 12
// baseline (speedup 1.0000x reference)
#include <cuda_runtime.h>
#include <cuda_bf16.h>
#include <math.h>

// Router: N=8192 tokens, C=1024, E=8 experts, top-2, cap=2560.
// Output (float32): [used_capacity(8) | cb_weight(N*E*cap) | sec_mask(N*E*cap)]

#define C_EMB 1024
#define N_EXP 8
#define TOPK  2
#define MAXN  8192
#define GEMM_BLKS 256
#define TILE_F4  2048                     // 32KB fill tile per warp-ticket

// Scratch (priority order i = k*N + n)
__device__ int      g_idx  [TOPK * MAXN];
__device__ float    g_prob [TOPK * MAXN];
__device__ unsigned g_ticket;             // reset each launch via memsetAsync

// ---------------------------------------------------------------------------
// Kernel 1 (R8-proven, 196.1us @ 84.6% DRAM): blocks [0,GEMM_BLKS) compute
// router logits+top2+softmax into scratch, then ALL blocks zero-fill the
// output via per-warp 32KB ticketed tiles (work stealing absorbs gemm time).
// No end-of-kernel synchronization — blocks retire as soon as tiles run out.
// ---------------------------------------------------------------------------
__global__ __launch_bounds__(256) void fused_fill_gemm(
    float4* __restrict__ out4, long n4,
    const float* __restrict__ x, const float* __restrict__ wg, int N)
{
    const int lane = threadIdx.x & 31;
    const int w    = threadIdx.x >> 5;

    if (blockIdx.x < GEMM_BLKS) {
        const int warp_g = blockIdx.x * 8 + w;   // 2048 warps, 4 tokens each
        for (int t = 0; t < 4; t++) {
            const int n = warp_g + t * (GEMM_BLKS * 8);
            if (n >= N) break;
            const float4* xr = reinterpret_cast<const float4*>(x + (size_t)n * C_EMB);
            float acc[N_EXP];
#pragma unroll
            for (int e = 0; e < N_EXP; e++) acc[e] = 0.f;
#pragma unroll
            for (int it = 0; it < C_EMB / (32 * 4); it++) {
                float4 v = xr[lane + it * 32];
#pragma unroll
                for (int e = 0; e < N_EXP; e++) {
                    float4 ww = __ldg(reinterpret_cast<const float4*>(wg + e * C_EMB) + lane + it * 32);
                    acc[e] += v.x * ww.x + v.y * ww.y + v.z * ww.z + v.w * ww.w;
                }
            }
#pragma unroll
            for (int off = 16; off; off >>= 1)
#pragma unroll
                for (int e = 0; e < N_EXP; e++)
                    acc[e] += __shfl_xor_sync(0xffffffffu, acc[e], off);

            if (lane == 0) {
                int e0 = 0; float l0 = acc[0];
#pragma unroll
                for (int e = 1; e < N_EXP; e++) if (acc[e] > l0) { l0 = acc[e]; e0 = e; }
                int e1 = -1; float l1 = -INFINITY;
#pragma unroll
                for (int e = 0; e < N_EXP; e++) if (e != e0 && acc[e] > l1) { l1 = acc[e]; e1 = e; }
                float tt  = __expf(l1 - l0);      // <= 1
                float inv = 1.f / (1.f + tt);
                g_idx [n]     = e0;  g_prob[n]     = inv;
                g_idx [N + n] = e1;  g_prob[N + n] = tt * inv;
            }
        }
    }

    // --- fill phase: per-warp ticketed 32KB tiles, streaming stores ---
    const float4 z = make_float4(0.f, 0.f, 0.f, 0.f);
    for (;;) {
        unsigned t;
        if (lane == 0) t = atomicAdd(&g_ticket, 1u);
        t = __shfl_sync(0xffffffffu, t, 0);
        long base = (long)t * TILE_F4;
        if (base >= n4) break;
        long end = base + TILE_F4 < n4 ? base + TILE_F4 : n4;
#pragma unroll 4
        for (long i = base + lane; i < end; i += 32)
            __stcs(&out4[i], z);
    }
}

// ---------------------------------------------------------------------------
// Kernel 2: rank + scatter in ONE launch, no cross-block dependency.
// Block b derives its global per-expert offset by re-counting the preceding
// b*256 indices (<=63KB, L2-resident), then ranks its own 256 items via
// __match_any_sync and scatters. Block (rblocks-1) also has grand totals
// (pre + own) and writes used_capacity.
// ---------------------------------------------------------------------------
__global__ __launch_bounds__(256) void rank_scatter(
    float* __restrict__ out, int N, int cap)
{
    const int tid  = threadIdx.x;
    const int lane = tid & 31;
    const int w    = tid >> 5;               // 8 warps
    const int bid  = blockIdx.x;
    const int rblocks = (TOPK * N) / 256;    // 64

    __shared__ int s_pre  [N_EXP];           // counts of experts in items [0, bid*256)
    __shared__ int s_whist[8][N_EXP];        // own-chunk per-warp histograms

    // ---- Phase 1: preceding-count histogram ----
    if (tid < N_EXP) s_pre[tid] = 0;
    if (tid < 8 * N_EXP) ((int*)s_whist)[tid] = 0;
    __syncthreads();

    {
        int cnt[N_EXP];
#pragma unroll
        for (int e = 0; e < N_EXP; e++) cnt[e] = 0;
        const int pre_items = bid * 256;
        for (int j = tid; j < pre_items; j += 256) cnt[g_idx[j]]++;
        // warp-reduce each counter, one shared atomic per warp per expert
#pragma unroll
        for (int e = 0; e < N_EXP; e++) {
            int v = cnt[e];
#pragma unroll
            for (int off = 16; off; off >>= 1) v += __shfl_xor_sync(0xffffffffu, v, off);
            if (lane == 0 && v) atomicAdd(&s_pre[e], v);
        }
    }

    // ---- Phase 2: own-chunk local rank (priority order == item order) ----
    const int i = bid * 256 + tid;
    int e = g_idx[i];
    float p = g_prob[i];
    unsigned m = __match_any_sync(0xffffffffu, e);
    int lrank = __popc(m & ((1u << lane) - 1u));

    if (lane == (__ffs(m) - 1)) s_whist[w][e] = __popc(m);
    __syncthreads();

    int woff = 0;
#pragma unroll
    for (int w2 = 0; w2 < 8; w2++)
        if (w2 < w) woff += s_whist[w2][e];

    // ---- used_capacity from the last block (pre + own = grand total) ----
    if (bid == rblocks - 1 && tid < N_EXP) {
        int tot = s_pre[tid];
#pragma unroll
        for (int w2 = 0; w2 < 8; w2++) tot += s_whist[w2][tid];
        out[tid] = (float)(tot < cap ? tot : cap);
    }

    // ---- Phase 3: capacity drop + sparse scatter ----
    int r = s_pre[e] + woff + lrank;
    if (r < cap) {
        int n = i & (N - 1);                 // i = k*N + n, N power of 2
        size_t o = (size_t)N_EXP + (size_t)n * (N_EXP * cap) + (size_t)e * cap + r;
        out[o] = p;
        out[o + (size_t)N * N_EXP * cap] = (p != 0.f) ? 1.f : 0.f;
    }
}

// ---------------------------------------------------------------------------
extern "C" void kernel_launch(void* const* d_in, const int* in_sizes, int n_in,
                              void* d_out, int out_size)
{
    const float* x  = (const float*)d_in[0];
    const float* wg = (const float*)d_in[1];
    int N = in_sizes[0] / C_EMB;      // 8192

    int cap = (5 * N) / 16;           // floor(2 * 1.25 * N / 8)
    cap += (cap & 1);
    if (cap < 4) cap = 4;

    // Reset the fill ticket counter
    void* tick_addr = nullptr;
    cudaGetSymbolAddress(&tick_addr, g_ticket);
    cudaMemsetAsync(tick_addr, 0, sizeof(unsigned), 0);

    // 1) fused: zero-fill whole output + router gemm/top2/softmax (scratch)
    long n4 = (long)out_size / 4;
    fused_fill_gemm<<<148 * 8, 256>>>((float4*)d_out, n4, x, wg, N);

    // 2) rank + scatter + used_capacity, single launch
    int rblocks = (TOPK * N) / 256;   // 64
    rank_scatter<<<rblocks, 256>>>((float*)d_out, N, cap);
}

// round 14
// speedup vs baseline: 1.0390x; 1.0390x over previous
#include <cuda_runtime.h>
#include <cuda_bf16.h>
#include <math.h>

// Router: N=8192 tokens, C=1024, E=8 experts, top-2, cap=2560.
// Output (float32): [used_capacity(8) | cb_weight(N*E*cap) | sec_mask(N*E*cap)]

#define C_EMB 1024
#define N_EXP 8
#define TOPK  2
#define MAXN  8192
#define GEMM_BLKS 256
#define TILE_F4  2048                     // 32KB fill tile per warp-ticket

// Scratch (priority order i = k*N + n)
__device__ int      g_idx  [TOPK * MAXN];
__device__ float    g_prob [TOPK * MAXN];
__device__ unsigned g_ticket;             // reset each launch via memsetAsync

// ---------------------------------------------------------------------------
// Kernel 1 (R8-proven, 196.1us @ 84.6% DRAM): blocks [0,GEMM_BLKS) compute
// router logits+top2+softmax into scratch, then ALL blocks zero-fill the
// output via per-warp 32KB ticketed tiles (work stealing absorbs gemm time).
// No end-of-kernel synchronization — blocks retire as soon as tiles run out.
// ---------------------------------------------------------------------------
__global__ __launch_bounds__(256) void fused_fill_gemm(
    float4* __restrict__ out4, long n4,
    const float* __restrict__ x, const float* __restrict__ wg, int N)
{
    const int lane = threadIdx.x & 31;
    const int w    = threadIdx.x >> 5;

    if (blockIdx.x < GEMM_BLKS) {
        const int warp_g = blockIdx.x * 8 + w;   // 2048 warps, 4 tokens each
        for (int t = 0; t < 4; t++) {
            const int n = warp_g + t * (GEMM_BLKS * 8);
            if (n >= N) break;
            const float4* xr = reinterpret_cast<const float4*>(x + (size_t)n * C_EMB);
            float acc[N_EXP];
#pragma unroll
            for (int e = 0; e < N_EXP; e++) acc[e] = 0.f;
#pragma unroll
            for (int it = 0; it < C_EMB / (32 * 4); it++) {
                float4 v = xr[lane + it * 32];
#pragma unroll
                for (int e = 0; e < N_EXP; e++) {
                    float4 ww = __ldg(reinterpret_cast<const float4*>(wg + e * C_EMB) + lane + it * 32);
                    acc[e] += v.x * ww.x + v.y * ww.y + v.z * ww.z + v.w * ww.w;
                }
            }
#pragma unroll
            for (int off = 16; off; off >>= 1)
#pragma unroll
                for (int e = 0; e < N_EXP; e++)
                    acc[e] += __shfl_xor_sync(0xffffffffu, acc[e], off);

            if (lane == 0) {
                int e0 = 0; float l0 = acc[0];
#pragma unroll
                for (int e = 1; e < N_EXP; e++) if (acc[e] > l0) { l0 = acc[e]; e0 = e; }
                int e1 = -1; float l1 = -INFINITY;
#pragma unroll
                for (int e = 0; e < N_EXP; e++) if (e != e0 && acc[e] > l1) { l1 = acc[e]; e1 = e; }
                float tt  = __expf(l1 - l0);      // <= 1
                float inv = 1.f / (1.f + tt);
                g_idx [n]     = e0;  g_prob[n]     = inv;
                g_idx [N + n] = e1;  g_prob[N + n] = tt * inv;
            }
        }
    }

    // --- fill phase: per-warp ticketed 32KB tiles, streaming stores ---
    const float4 z = make_float4(0.f, 0.f, 0.f, 0.f);
    for (;;) {
        unsigned t;
        if (lane == 0) t = atomicAdd(&g_ticket, 1u);
        t = __shfl_sync(0xffffffffu, t, 0);
        long base = (long)t * TILE_F4;
        if (base >= n4) break;
        long end = base + TILE_F4 < n4 ? base + TILE_F4 : n4;
#pragma unroll 4
        for (long i = base + lane; i < end; i += 32)
            __stcs(&out4[i], z);
    }
}

// ---------------------------------------------------------------------------
// Kernel 2: rank + scatter in ONE launch, no cross-block dependency.
// Block b derives its global per-expert offset by re-counting the preceding
// b*256 indices (L2-resident, coalesced). Histogram kept in REGISTERS via
// compile-time-unrolled compare-adds (a dynamic index here demotes the array
// to local memory — that was R12's 22us pathology).
// ---------------------------------------------------------------------------
__global__ __launch_bounds__(256) void rank_scatter(
    float* __restrict__ out, int N, int cap)
{
    const int tid  = threadIdx.x;
    const int lane = tid & 31;
    const int w    = tid >> 5;               // 8 warps
    const int bid  = blockIdx.x;
    const int rblocks = (TOPK * N) / 256;    // 64

    __shared__ int s_pre  [N_EXP];           // counts of experts in items [0, bid*256)
    __shared__ int s_whist[8][N_EXP];        // own-chunk per-warp histograms

    if (tid < N_EXP) s_pre[tid] = 0;
    if (tid < 8 * N_EXP) ((int*)s_whist)[tid] = 0;
    __syncthreads();

    // ---- Phase 1: preceding-count histogram (registers only) ----
    {
        int cnt[N_EXP];
#pragma unroll
        for (int e = 0; e < N_EXP; e++) cnt[e] = 0;
        const int pre_items = bid * 256;
        for (int j = tid; j < pre_items; j += 256) {
            int v = g_idx[j];
#pragma unroll
            for (int e = 0; e < N_EXP; e++) cnt[e] += (v == e);
        }
        // warp-reduce each counter, one shared atomic per warp per expert
#pragma unroll
        for (int e = 0; e < N_EXP; e++) {
            int v = cnt[e];
#pragma unroll
            for (int off = 16; off; off >>= 1) v += __shfl_xor_sync(0xffffffffu, v, off);
            if (lane == 0 && v) atomicAdd(&s_pre[e], v);
        }
    }

    // ---- Phase 2: own-chunk local rank (priority order == item order) ----
    const int i = bid * 256 + tid;
    int e = g_idx[i];
    float p = g_prob[i];
    unsigned m = __match_any_sync(0xffffffffu, e);
    int lrank = __popc(m & ((1u << lane) - 1u));

    if (lane == (__ffs(m) - 1)) s_whist[w][e] = __popc(m);
    __syncthreads();

    int woff = 0;
#pragma unroll
    for (int w2 = 0; w2 < 8; w2++)
        if (w2 < w) woff += s_whist[w2][e];

    // ---- used_capacity from the last block (pre + own = grand total) ----
    if (bid == rblocks - 1 && tid < N_EXP) {
        int tot = s_pre[tid];
#pragma unroll
        for (int w2 = 0; w2 < 8; w2++) tot += s_whist[w2][tid];
        out[tid] = (float)(tot < cap ? tot : cap);
    }

    // ---- Phase 3: capacity drop + sparse scatter ----
    int r = s_pre[e] + woff + lrank;
    if (r < cap) {
        int n = i & (N - 1);                 // i = k*N + n, N power of 2
        size_t o = (size_t)N_EXP + (size_t)n * (N_EXP * cap) + (size_t)e * cap + r;
        out[o] = p;
        out[o + (size_t)N * N_EXP * cap] = (p != 0.f) ? 1.f : 0.f;
    }
}

// ---------------------------------------------------------------------------
extern "C" void kernel_launch(void* const* d_in, const int* in_sizes, int n_in,
                              void* d_out, int out_size)
{
    const float* x  = (const float*)d_in[0];
    const float* wg = (const float*)d_in[1];
    int N = in_sizes[0] / C_EMB;      // 8192

    int cap = (5 * N) / 16;           // floor(2 * 1.25 * N / 8)
    cap += (cap & 1);
    if (cap < 4) cap = 4;

    // Reset the fill ticket counter
    void* tick_addr = nullptr;
    cudaGetSymbolAddress(&tick_addr, g_ticket);
    cudaMemsetAsync(tick_addr, 0, sizeof(unsigned), 0);

    // 1) fused: zero-fill whole output + router gemm/top2/softmax (scratch)
    long n4 = (long)out_size / 4;
    fused_fill_gemm<<<148 * 8, 256>>>((float4*)d_out, n4, x, wg, N);

    // 2) rank + scatter + used_capacity, single launch
    int rblocks = (TOPK * N) / 256;   // 64
    rank_scatter<<<rblocks, 256>>>((float*)d_out, N, cap);
}

// round 15
// speedup vs baseline: 1.0648x; 1.0248x over previous
#include <cuda_runtime.h>
#include <cuda_bf16.h>
#include <math.h>

// Router: N=8192 tokens, C=1024, E=8 experts, top-2, cap=2560.
// Output (float32): [used_capacity(8) | cb_weight(N*E*cap) | sec_mask(N*E*cap)]

#define C_EMB 1024
#define N_EXP 8
#define TOPK  2
#define MAXN  8192
#define GEMM_BLKS 256
#define RBLKS   ((TOPK * MAXN) / 256)     // 64 chunks of 256 items
#define TILE_F4  2048                     // 32KB fill tile per warp-ticket

// Scratch (priority order i = k*N + n)
__device__ int   g_idx  [TOPK * MAXN];
__device__ float g_prob [TOPK * MAXN];
// [0] = fill ticket, [1..512] = per-(chunk,expert) histogram. One memset resets all.
__device__ int   g_meta [1 + RBLKS * N_EXP];

// ---------------------------------------------------------------------------
// Kernel 1: gemm phase (blocks 0..255) computes logits+top2+softmax AND
// accumulates per-(chunk,expert) histograms via global atomics (hidden under
// the fill). Then ALL blocks zero-fill the output via ticketed 32KB tiles.
// No end-of-kernel synchronization.
// ---------------------------------------------------------------------------
__global__ __launch_bounds__(256) void fused_fill_gemm(
    float4* __restrict__ out4, long n4,
    const float* __restrict__ x, const float* __restrict__ wg, int N)
{
    const int lane = threadIdx.x & 31;
    const int w    = threadIdx.x >> 5;

    if (blockIdx.x < GEMM_BLKS) {
        const int warp_g = blockIdx.x * 8 + w;   // 2048 warps, 4 tokens each
        for (int t = 0; t < 4; t++) {
            const int n = warp_g + t * (GEMM_BLKS * 8);
            if (n >= N) break;
            const float4* xr = reinterpret_cast<const float4*>(x + (size_t)n * C_EMB);
            float acc[N_EXP];
#pragma unroll
            for (int e = 0; e < N_EXP; e++) acc[e] = 0.f;
#pragma unroll
            for (int it = 0; it < C_EMB / (32 * 4); it++) {
                float4 v = xr[lane + it * 32];
#pragma unroll
                for (int e = 0; e < N_EXP; e++) {
                    float4 ww = __ldg(reinterpret_cast<const float4*>(wg + e * C_EMB) + lane + it * 32);
                    acc[e] += v.x * ww.x + v.y * ww.y + v.z * ww.z + v.w * ww.w;
                }
            }
#pragma unroll
            for (int off = 16; off; off >>= 1)
#pragma unroll
                for (int e = 0; e < N_EXP; e++)
                    acc[e] += __shfl_xor_sync(0xffffffffu, acc[e], off);

            if (lane == 0) {
                int e0 = 0; float l0 = acc[0];
#pragma unroll
                for (int e = 1; e < N_EXP; e++) if (acc[e] > l0) { l0 = acc[e]; e0 = e; }
                int e1 = -1; float l1 = -INFINITY;
#pragma unroll
                for (int e = 0; e < N_EXP; e++) if (e != e0 && acc[e] > l1) { l1 = acc[e]; e1 = e; }
                float tt  = __expf(l1 - l0);      // <= 1
                float inv = 1.f / (1.f + tt);
                g_idx [n]     = e0;  g_prob[n]     = inv;
                g_idx [N + n] = e1;  g_prob[N + n] = tt * inv;
                // chunk histograms (chunk = item_index >> 8), consumed by kernel 2
                atomicAdd(&g_meta[1 + (n >> 8) * N_EXP + e0], 1);
                atomicAdd(&g_meta[1 + ((N + n) >> 8) * N_EXP + e1], 1);
            }
        }
    }

    // --- fill phase: per-warp ticketed 32KB tiles, streaming stores ---
    const float4 z = make_float4(0.f, 0.f, 0.f, 0.f);
    unsigned* ticket = (unsigned*)&g_meta[0];
    for (;;) {
        unsigned t;
        if (lane == 0) t = atomicAdd(ticket, 1u);
        t = __shfl_sync(0xffffffffu, t, 0);
        long base = (long)t * TILE_F4;
        if (base >= n4) break;
        long end = base + TILE_F4 < n4 ? base + TILE_F4 : n4;
#pragma unroll 4
        for (long i = base + lane; i < end; i += 32)
            __stcs(&out4[i], z);
    }
}

// ---------------------------------------------------------------------------
// Kernel 2: per-block prefix from precomputed chunk histograms (warp-per-
// expert shuffle scan over 64 chunks), local rank via __match_any_sync,
// capacity drop, sparse scatter, used_capacity. Balanced: every block
// touches ~4KB.
// ---------------------------------------------------------------------------
__global__ __launch_bounds__(256) void rank_scatter(
    float* __restrict__ out, int N, int cap)
{
    const int tid  = threadIdx.x;
    const int lane = tid & 31;
    const int w    = tid >> 5;               // 8 warps == 8 experts
    const int bid  = blockIdx.x;
    const int rblocks = (TOPK * N) / 256;    // 64

    __shared__ int s_boff [N_EXP];           // sum of counts in chunks [0, bid) per expert
    __shared__ int s_tot  [N_EXP];           // grand totals
    __shared__ int s_whist[8][N_EXP];        // own-chunk per-warp histograms

    if (tid < 8 * N_EXP) ((int*)s_whist)[tid] = 0;

    // warp w scans expert w over 64 chunk counts (2 per lane)
    {
        const int* bh = &g_meta[1];
        int b0 = 2 * lane, b1 = 2 * lane + 1;
        int c0 = (b0 < rblocks) ? bh[b0 * N_EXP + w] : 0;
        int c1 = (b1 < rblocks) ? bh[b1 * N_EXP + w] : 0;
        int pair = c0 + c1;
        int scan = pair;                     // inclusive scan of pairs
#pragma unroll
        for (int off = 1; off < 32; off <<= 1) {
            int v = __shfl_up_sync(0xffffffffu, scan, off);
            if (lane >= off) scan += v;
        }
        int excl  = scan - pair;             // sum of chunks [0, 2*lane)
        int srcl  = bid >> 1;
        int exclv = __shfl_sync(0xffffffffu, excl, srcl);
        int c0v   = __shfl_sync(0xffffffffu, c0,   srcl);
        int off_b = exclv + ((bid & 1) ? c0v : 0);
        int total = __shfl_sync(0xffffffffu, scan, 31);
        if (lane == 0) { s_boff[w] = off_b; s_tot[w] = total; }
    }
    __syncthreads();

    if (bid == 0 && tid < N_EXP) {
        int u = s_tot[tid];
        out[tid] = (float)(u < cap ? u : cap);   // used_capacity
    }

    // own-chunk local rank (priority order == item order within the chunk)
    const int i = bid * 256 + tid;
    int e = g_idx[i];
    float p = g_prob[i];
    unsigned m = __match_any_sync(0xffffffffu, e);
    int lrank = __popc(m & ((1u << lane) - 1u));

    if (lane == (__ffs(m) - 1)) s_whist[w][e] = __popc(m);
    __syncthreads();

    int woff = 0;
#pragma unroll
    for (int w2 = 0; w2 < 8; w2++)
        if (w2 < w) woff += s_whist[w2][e];

    int r = s_boff[e] + woff + lrank;
    if (r < cap) {
        int n = i & (N - 1);                 // i = k*N + n, N power of 2
        size_t o = (size_t)N_EXP + (size_t)n * (N_EXP * cap) + (size_t)e * cap + r;
        out[o] = p;
        out[o + (size_t)N * N_EXP * cap] = (p != 0.f) ? 1.f : 0.f;
    }
}

// ---------------------------------------------------------------------------
extern "C" void kernel_launch(void* const* d_in, const int* in_sizes, int n_in,
                              void* d_out, int out_size)
{
    const float* x  = (const float*)d_in[0];
    const float* wg = (const float*)d_in[1];
    int N = in_sizes[0] / C_EMB;      // 8192

    int cap = (5 * N) / 16;           // floor(2 * 1.25 * N / 8)
    cap += (cap & 1);
    if (cap < 4) cap = 4;

    // Reset ticket + chunk histograms in one async memset (2.1KB)
    void* meta_addr = nullptr;
    cudaGetSymbolAddress(&meta_addr, g_meta);
    cudaMemsetAsync(meta_addr, 0, (1 + RBLKS * N_EXP) * sizeof(int), 0);

    // 1) fused: zero-fill + gemm/top2/softmax + chunk histograms
    long n4 = (long)out_size / 4;
    fused_fill_gemm<<<148 * 8, 256>>>((float4*)d_out, n4, x, wg, N);

    // 2) prefix + rank + scatter + used_capacity (balanced, ~4KB per block)
    rank_scatter<<<RBLKS, 256>>>((float*)d_out, N, cap);
}

// round 16
// speedup vs baseline: 1.0741x; 1.0087x over previous
#include <cuda_runtime.h>
#include <cuda_bf16.h>
#include <math.h>

// Router: N=8192 tokens, C=1024, E=8 experts, top-2, cap=2560.
// Output (float32): [used_capacity(8) | cb_weight(N*E*cap) | sec_mask(N*E*cap)]

#define C_EMB 1024
#define N_EXP 8
#define TOPK  2
#define MAXN  8192
#define GEMM_BLKS 256
#define RBLKS   ((TOPK * MAXN) / 256)     // 64 chunks of 256 items
#define TILE_F4  2048                     // 32KB fill tile per warp-ticket

// Scratch (priority order i = k*N + n)
__device__ int   g_idx  [TOPK * MAXN];
__device__ float g_prob [TOPK * MAXN];
// [0] = fill ticket, [1..512] = per-(chunk,expert) histogram. One memset resets all.
__device__ int   g_meta [1 + RBLKS * N_EXP];

// ---------------------------------------------------------------------------
// Kernel 1: gemm phase (blocks 0..255) computes logits+top2+softmax AND
// accumulates per-(chunk,expert) histograms via global atomics (hidden under
// the fill). Then ALL blocks zero-fill the output via ticketed 32KB tiles.
// No end-of-kernel synchronization.
// ---------------------------------------------------------------------------
__global__ __launch_bounds__(256) void fused_fill_gemm(
    float4* __restrict__ out4, long n4,
    const float* __restrict__ x, const float* __restrict__ wg, int N)
{
    const int lane = threadIdx.x & 31;
    const int w    = threadIdx.x >> 5;

    if (blockIdx.x < GEMM_BLKS) {
        const int warp_g = blockIdx.x * 8 + w;   // 2048 warps, 4 tokens each
        for (int t = 0; t < 4; t++) {
            const int n = warp_g + t * (GEMM_BLKS * 8);
            if (n >= N) break;
            const float4* xr = reinterpret_cast<const float4*>(x + (size_t)n * C_EMB);
            float acc[N_EXP];
#pragma unroll
            for (int e = 0; e < N_EXP; e++) acc[e] = 0.f;
#pragma unroll
            for (int it = 0; it < C_EMB / (32 * 4); it++) {
                float4 v = xr[lane + it * 32];
#pragma unroll
                for (int e = 0; e < N_EXP; e++) {
                    float4 ww = __ldg(reinterpret_cast<const float4*>(wg + e * C_EMB) + lane + it * 32);
                    acc[e] += v.x * ww.x + v.y * ww.y + v.z * ww.z + v.w * ww.w;
                }
            }
#pragma unroll
            for (int off = 16; off; off >>= 1)
#pragma unroll
                for (int e = 0; e < N_EXP; e++)
                    acc[e] += __shfl_xor_sync(0xffffffffu, acc[e], off);

            if (lane == 0) {
                int e0 = 0; float l0 = acc[0];
#pragma unroll
                for (int e = 1; e < N_EXP; e++) if (acc[e] > l0) { l0 = acc[e]; e0 = e; }
                int e1 = -1; float l1 = -INFINITY;
#pragma unroll
                for (int e = 0; e < N_EXP; e++) if (e != e0 && acc[e] > l1) { l1 = acc[e]; e1 = e; }
                float tt  = __expf(l1 - l0);      // <= 1
                float inv = 1.f / (1.f + tt);
                g_idx [n]     = e0;  g_prob[n]     = inv;
                g_idx [N + n] = e1;  g_prob[N + n] = tt * inv;
                // chunk histograms (chunk = item_index >> 8), consumed by kernel 2
                atomicAdd(&g_meta[1 + (n >> 8) * N_EXP + e0], 1);
                atomicAdd(&g_meta[1 + ((N + n) >> 8) * N_EXP + e1], 1);
            }
        }
    }

    // --- fill phase: per-warp ticketed 32KB tiles, streaming stores ---
    const float4 z = make_float4(0.f, 0.f, 0.f, 0.f);
    unsigned* ticket = (unsigned*)&g_meta[0];
    for (;;) {
        unsigned t;
        if (lane == 0) t = atomicAdd(ticket, 1u);
        t = __shfl_sync(0xffffffffu, t, 0);
        long base = (long)t * TILE_F4;
        if (base >= n4) break;
        long end = base + TILE_F4 < n4 ? base + TILE_F4 : n4;
#pragma unroll 4
        for (long i = base + lane; i < end; i += 32)
            __stcs(&out4[i], z);
    }
}

// ---------------------------------------------------------------------------
// Kernel 2 (PDL secondary): launched with programmatic stream serialization so
// its blocks are resident and warmed up BEFORE the primary finishes; the
// grid-dependency sync releases at primary completion, then ~3us of work.
// Prefix from precomputed chunk histograms (warp-per-expert shuffle scan),
// local rank via __match_any_sync, capacity drop, scatter, used_capacity.
// ---------------------------------------------------------------------------
__global__ __launch_bounds__(256) void rank_scatter(
    float* __restrict__ out, int N, int cap)
{
    const int tid  = threadIdx.x;
    const int lane = tid & 31;
    const int w    = tid >> 5;               // 8 warps == 8 experts
    const int bid  = blockIdx.x;
    const int rblocks = (TOPK * N) / 256;    // 64

    __shared__ int s_boff [N_EXP];           // sum of counts in chunks [0, bid) per expert
    __shared__ int s_tot  [N_EXP];           // grand totals
    __shared__ int s_whist[8][N_EXP];        // own-chunk per-warp histograms

    if (tid < 8 * N_EXP) ((int*)s_whist)[tid] = 0;

    // Wait for the primary kernel (fill + gemm + histograms) to fully complete.
    // Everything above overlapped with the primary's fill phase.
    cudaGridDependencySynchronize();

    // warp w scans expert w over 64 chunk counts (2 per lane)
    {
        const int* bh = &g_meta[1];
        int b0 = 2 * lane, b1 = 2 * lane + 1;
        int c0 = (b0 < rblocks) ? bh[b0 * N_EXP + w] : 0;
        int c1 = (b1 < rblocks) ? bh[b1 * N_EXP + w] : 0;
        int pair = c0 + c1;
        int scan = pair;                     // inclusive scan of pairs
#pragma unroll
        for (int off = 1; off < 32; off <<= 1) {
            int v = __shfl_up_sync(0xffffffffu, scan, off);
            if (lane >= off) scan += v;
        }
        int excl  = scan - pair;             // sum of chunks [0, 2*lane)
        int srcl  = bid >> 1;
        int exclv = __shfl_sync(0xffffffffu, excl, srcl);
        int c0v   = __shfl_sync(0xffffffffu, c0,   srcl);
        int off_b = exclv + ((bid & 1) ? c0v : 0);
        int total = __shfl_sync(0xffffffffu, scan, 31);
        if (lane == 0) { s_boff[w] = off_b; s_tot[w] = total; }
    }
    __syncthreads();

    if (bid == 0 && tid < N_EXP) {
        int u = s_tot[tid];
        out[tid] = (float)(u < cap ? u : cap);   // used_capacity
    }

    // own-chunk local rank (priority order == item order within the chunk)
    const int i = bid * 256 + tid;
    int e = g_idx[i];
    float p = g_prob[i];
    unsigned m = __match_any_sync(0xffffffffu, e);
    int lrank = __popc(m & ((1u << lane) - 1u));

    if (lane == (__ffs(m) - 1)) s_whist[w][e] = __popc(m);
    __syncthreads();

    int woff = 0;
#pragma unroll
    for (int w2 = 0; w2 < 8; w2++)
        if (w2 < w) woff += s_whist[w2][e];

    int r = s_boff[e] + woff + lrank;
    if (r < cap) {
        int n = i & (N - 1);                 // i = k*N + n, N power of 2
        size_t o = (size_t)N_EXP + (size_t)n * (N_EXP * cap) + (size_t)e * cap + r;
        out[o] = p;
        out[o + (size_t)N * N_EXP * cap] = (p != 0.f) ? 1.f : 0.f;
    }
}

// ---------------------------------------------------------------------------
extern "C" void kernel_launch(void* const* d_in, const int* in_sizes, int n_in,
                              void* d_out, int out_size)
{
    const float* x  = (const float*)d_in[0];
    const float* wg = (const float*)d_in[1];
    int N = in_sizes[0] / C_EMB;      // 8192

    int cap = (5 * N) / 16;           // floor(2 * 1.25 * N / 8)
    cap += (cap & 1);
    if (cap < 4) cap = 4;

    // Reset ticket + chunk histograms in one async memset (2.1KB)
    void* meta_addr = nullptr;
    cudaGetSymbolAddress(&meta_addr, g_meta);
    cudaMemsetAsync(meta_addr, 0, (1 + RBLKS * N_EXP) * sizeof(int), 0);

    // 1) fused: zero-fill + gemm/top2/softmax + chunk histograms
    long n4 = (long)out_size / 4;
    fused_fill_gemm<<<148 * 8, 256>>>((float4*)d_out, n4, x, wg, N);

    // 2) rank + scatter, launched as a PDL secondary so launch/ramp overlap
    //    with the primary's fill phase.
    cudaLaunchAttribute attrs[1];
    attrs[0].id = cudaLaunchAttributeProgrammaticStreamSerialization;
    attrs[0].val.programmaticStreamSerializationAllowed = 1;

    cudaLaunchConfig_t cfg = {};
    cfg.gridDim  = dim3(RBLKS, 1, 1);
    cfg.blockDim = dim3(256, 1, 1);
    cfg.dynamicSmemBytes = 0;
    cfg.stream   = 0;
    cfg.attrs    = attrs;
    cfg.numAttrs = 1;
    cudaLaunchKernelEx(&cfg, rank_scatter, (float*)d_out, N, cap);
}